// round 1
// baseline (speedup 1.0000x reference)
#include <cuda_runtime.h>
#include <cstdint>
#include <cstddef>

#define NUM_HEADS 8
#define NTOK 50
#define HEADDIM 32
#define NWIN 2048
#define CDIM 256

// Scratch (allocation-free rule: __device__ globals)
__device__ float g_qkv[3ULL * NWIN * NUM_HEADS * NTOK * HEADDIM];  // [which][b][h][t][d]
__device__ float g_att[(size_t)NWIN * NTOK * CDIM];                // [b][t][h*32+d]
__device__ float g_bias[NUM_HEADS * NTOK * NTOK];                  // padded bias [h][i][j]

__device__ __forceinline__ uint32_t f2tf32(float f) {
    uint32_t r;
    asm("cvt.rna.tf32.f32 %0, %1;" : "=r"(r) : "f"(f));
    return r;
}

__device__ __forceinline__ void mma_tf32(float d[4], const uint32_t a[4], const uint32_t b[2]) {
    asm volatile(
        "mma.sync.aligned.m16n8k8.row.col.f32.tf32.tf32.f32 "
        "{%0,%1,%2,%3}, {%4,%5,%6,%7}, {%8,%9}, {%0,%1,%2,%3};\n"
        : "+f"(d[0]), "+f"(d[1]), "+f"(d[2]), "+f"(d[3])
        : "r"(a[0]), "r"(a[1]), "r"(a[2]), "r"(a[3]), "r"(b[0]), "r"(b[1]));
}

// ---------------------------------------------------------------------------
// Kernel 0: expand relative-position bias table -> [8][50][50], zero row/col 0
// ---------------------------------------------------------------------------
__global__ void bias_expand_kernel(const float* __restrict__ bt, const int* __restrict__ ridx) {
    int i = blockIdx.x * 256 + threadIdx.x;
    if (i >= NUM_HEADS * NTOK * NTOK) return;
    int h = i / (NTOK * NTOK);
    int rem = i - h * NTOK * NTOK;
    int r = rem / NTOK;
    int c = rem - r * NTOK;
    float v = 0.f;
    if (r > 0 && c > 0) {
        int idx = ridx[(r - 1) * 49 + (c - 1)];
        v = bt[idx * NUM_HEADS + h];
    }
    g_bias[i] = v;
}

// ---------------------------------------------------------------------------
// Kernels 1 & 3: tf32 GEMM  C[M, N] = A[M,256] @ W[N,256]^T + bias
//   epi==0: QKV (N=768), scatter to g_qkv with q pre-scaled
//   epi==1: proj (N=256), A = g_att, write d_out
// Tiles: BM=64, BN=64, BK=16; 4 warps (2x2), warp tile 32x32, mma m16n8k8.
// ---------------------------------------------------------------------------
__global__ __launch_bounds__(128) void gemm_tf32_kernel(
    const float* __restrict__ A, const float* __restrict__ W,
    const float* __restrict__ bias, float* __restrict__ out, int epi)
{
    if (epi == 1) A = g_att;

    __shared__ uint32_t As[64 * 20];  // padded stride 20: conflict-free frag loads
    __shared__ uint32_t Bs[64 * 20];

    const int tid = threadIdx.x;
    const int lane = tid & 31;
    const int warp = tid >> 5;
    const int wm = warp >> 1, wn = warp & 1;
    const int bm = blockIdx.y, bn = blockIdx.x;

    float acc[2][4][4];
#pragma unroll
    for (int i = 0; i < 2; i++)
#pragma unroll
        for (int j = 0; j < 4; j++)
#pragma unroll
            for (int r = 0; r < 4; r++) acc[i][j][r] = 0.f;

    const float* Ag = A + (size_t)bm * 64 * 256;
    const float* Wg = W + (size_t)bn * 64 * 256;
    const int r0 = tid >> 1;          // smem tile row this thread fills
    const int c0 = (tid & 1) * 8;     // 8 cols (two float4) per thread

    for (int kt = 0; kt < 16; kt++) {
        const int k0 = kt * 16;
        float4 av0 = *(const float4*)(Ag + (size_t)r0 * 256 + k0 + c0);
        float4 av1 = *(const float4*)(Ag + (size_t)r0 * 256 + k0 + c0 + 4);
        float4 bv0 = *(const float4*)(Wg + (size_t)r0 * 256 + k0 + c0);
        float4 bv1 = *(const float4*)(Wg + (size_t)r0 * 256 + k0 + c0 + 4);
        __syncthreads();
        *(uint4*)(As + r0 * 20 + c0) =
            make_uint4(f2tf32(av0.x), f2tf32(av0.y), f2tf32(av0.z), f2tf32(av0.w));
        *(uint4*)(As + r0 * 20 + c0 + 4) =
            make_uint4(f2tf32(av1.x), f2tf32(av1.y), f2tf32(av1.z), f2tf32(av1.w));
        *(uint4*)(Bs + r0 * 20 + c0) =
            make_uint4(f2tf32(bv0.x), f2tf32(bv0.y), f2tf32(bv0.z), f2tf32(bv0.w));
        *(uint4*)(Bs + r0 * 20 + c0 + 4) =
            make_uint4(f2tf32(bv1.x), f2tf32(bv1.y), f2tf32(bv1.z), f2tf32(bv1.w));
        __syncthreads();

#pragma unroll
        for (int ks = 0; ks < 16; ks += 8) {
            uint32_t af[2][4], bf[4][2];
#pragma unroll
            for (int tm = 0; tm < 2; tm++) {
                int row = wm * 32 + tm * 16 + (lane >> 2);
                af[tm][0] = As[row * 20 + ks + (lane & 3)];
                af[tm][1] = As[(row + 8) * 20 + ks + (lane & 3)];
                af[tm][2] = As[row * 20 + ks + 4 + (lane & 3)];
                af[tm][3] = As[(row + 8) * 20 + ks + 4 + (lane & 3)];
            }
#pragma unroll
            for (int tn = 0; tn < 4; tn++) {
                int nr = wn * 32 + tn * 8 + (lane >> 2);
                bf[tn][0] = Bs[nr * 20 + ks + (lane & 3)];
                bf[tn][1] = Bs[nr * 20 + ks + 4 + (lane & 3)];
            }
#pragma unroll
            for (int tm = 0; tm < 2; tm++)
#pragma unroll
                for (int tn = 0; tn < 4; tn++) mma_tf32(acc[tm][tn], af[tm], bf[tn]);
        }
    }

    const float scale = 0.17677669529663687f;  // 32^-0.5
#pragma unroll
    for (int tm = 0; tm < 2; tm++)
#pragma unroll
        for (int tn = 0; tn < 4; tn++) {
            int m_g = bm * 64 + wm * 32 + tm * 16 + (lane >> 2);
            int n_g = bn * 64 + wn * 32 + tn * 8 + 2 * (lane & 3);
#pragma unroll
            for (int hf = 0; hf < 2; hf++) {
                int mm = m_g + hf * 8;
                float v0 = acc[tm][tn][hf * 2 + 0] + bias[n_g];
                float v1 = acc[tm][tn][hf * 2 + 1] + bias[n_g + 1];
                if (epi == 0) {
                    int which = n_g >> 8;
                    int rcol = n_g & 255;
                    int h = rcol >> 5, d = rcol & 31;
                    if (which == 0) { v0 *= scale; v1 *= scale; }
                    int b = mm / NTOK;
                    int t = mm - b * NTOK;
                    size_t idx = ((size_t)which * NWIN * NUM_HEADS + (size_t)b * NUM_HEADS + h)
                                     * (NTOK * HEADDIM)
                                 + t * HEADDIM + d;
                    *(float2*)(g_qkv + idx) = make_float2(v0, v1);
                } else {
                    *(float2*)(out + (size_t)mm * CDIM + n_g) = make_float2(v0, v1);
                }
            }
        }
}

// ---------------------------------------------------------------------------
// Kernel 2: fused attention per (window, head). 128 threads / block.
//   smem q/k/v padded to stride 36 (avoids 16-way row-stride conflicts);
//   bias preloaded into P buffer; softmax normalization folded into output.
// ---------------------------------------------------------------------------
__global__ __launch_bounds__(128) void attn_kernel() {
    const int bh = blockIdx.x;
    const int b = bh >> 3, h = bh & 7;

    __shared__ float qs[50 * 36];
    __shared__ float ks2[50 * 36];
    __shared__ float vs[50 * 36];
    __shared__ float Ps[50 * 52];
    __shared__ float redmax[50 * 2], redsum[50 * 2], rinv[50];

    const int tid = threadIdx.x;
    const size_t strideWH = (size_t)NWIN * NUM_HEADS * NTOK * HEADDIM;
    const float* qg = g_qkv + ((size_t)b * NUM_HEADS + h) * (NTOK * HEADDIM);
    const float* kg = qg + strideWH;
    const float* vg = kg + strideWH;

    for (int i = tid; i < 400; i += 128) {  // 50*32/4 float4s per array
        int r = i >> 3, c = (i & 7) * 4;
        *(float4*)(qs + r * 36 + c) = *(const float4*)(qg + i * 4);
        *(float4*)(ks2 + r * 36 + c) = *(const float4*)(kg + i * 4);
        *(float4*)(vs + r * 36 + c) = *(const float4*)(vg + i * 4);
    }
    const float* bg = g_bias + h * (NTOK * NTOK);
    for (int i = tid; i < NTOK * NTOK; i += 128) {
        int r = i / NTOK, c = i - r * NTOK;
        Ps[r * 52 + c] = bg[i];
    }
    __syncthreads();

    const int r = tid >> 1;
    const int half = tid & 1;
    float sv[25];
    if (r < 50) {
        float4 q4[8];
#pragma unroll
        for (int kk = 0; kk < 8; kk++) q4[kk] = *(const float4*)(qs + r * 36 + kk * 4);
        const int cbase = half * 25;
        float smax = -1e30f;
#pragma unroll
        for (int c = 0; c < 25; c++) {
            const float* kr = ks2 + (cbase + c) * 36;
            float a = Ps[r * 52 + cbase + c];  // bias
#pragma unroll
            for (int kk = 0; kk < 8; kk++) {
                float4 k4 = *(const float4*)(kr + kk * 4);
                a += q4[kk].x * k4.x + q4[kk].y * k4.y + q4[kk].z * k4.z + q4[kk].w * k4.w;
            }
            sv[c] = a;
            smax = fmaxf(smax, a);
        }
        redmax[r * 2 + half] = smax;
    }
    __syncthreads();
    if (r < 50) {
        float m = fmaxf(redmax[r * 2], redmax[r * 2 + 1]);
        const int cbase = half * 25;
        float s = 0.f;
#pragma unroll
        for (int c = 0; c < 25; c++) {
            float e = __expf(sv[c] - m);
            Ps[r * 52 + cbase + c] = e;
            s += e;
        }
        redsum[r * 2 + half] = s;
    }
    __syncthreads();
    if (tid < 50) rinv[tid] = 1.f / (redsum[tid * 2] + redsum[tid * 2 + 1]);
    __syncthreads();

    const int d = tid & 31;
    const int rw = tid >> 5;
    float* og = g_att + (size_t)b * NTOK * CDIM + h * HEADDIM + d;
    for (int rr = rw; rr < 50; rr += 4) {
        float a = 0.f;
        const float* pr = Ps + rr * 52;
#pragma unroll
        for (int c = 0; c < 50; c++) a += pr[c] * vs[c * 36 + d];
        og[(size_t)rr * CDIM] = a * rinv[rr];
    }
}

// ---------------------------------------------------------------------------
extern "C" void kernel_launch(void* const* d_in, const int* in_sizes, int n_in,
                              void* d_out, int out_size) {
    const float* x = (const float*)d_in[0];
    const float* qkv_w = (const float*)d_in[1];
    const float* qkv_b = (const float*)d_in[2];
    const float* proj_w = (const float*)d_in[3];
    const float* proj_b = (const float*)d_in[4];
    const float* bias_table = (const float*)d_in[5];
    const int* rel_idx = (const int*)d_in[6];
    float* out = (float*)d_out;

    (void)in_sizes; (void)n_in; (void)out_size;

    bias_expand_kernel<<<(NUM_HEADS * NTOK * NTOK + 255) / 256, 256>>>(bias_table, rel_idx);
    gemm_tf32_kernel<<<dim3(768 / 64, (NWIN * NTOK) / 64), 128>>>(x, qkv_w, qkv_b, nullptr, 0);
    attn_kernel<<<NWIN * NUM_HEADS, 128>>>();
    gemm_tf32_kernel<<<dim3(CDIM / 64, (NWIN * NTOK) / 64), 128>>>(nullptr, proj_w, proj_b, out, 1);
}